// round 4
// baseline (speedup 1.0000x reference)
#include <cuda_runtime.h>
#include <math.h>

#define Bc 2
#define Lc 2048
#define Tc 4096
#define DIMc 2048
#define Hc 16
#define KVHc 4
#define HDc 128
#define Ec 8
#define HIDc 8192
#define KVDc 512

#define BM 128
#define BN 128
#define BK 16
#define NTHR 256

// flash-attention tiling
#define FA_BQ 128
#define FA_BK 64

// ---------------- scratch (device globals; no allocations allowed) ----------
// total ~340 MB (round-0's 537 MB score tensor is gone — flash attention)
__device__ float g_xn[(size_t)Tc * DIMc];
__device__ float g_q [(size_t)Tc * DIMc];
__device__ float g_k [(size_t)Tc * KVDc];
__device__ float g_v [(size_t)Tc * KVDc];
__device__ float g_ao[(size_t)Tc * DIMc];
__device__ float g_h [(size_t)Tc * DIMc];
__device__ float g_hn[(size_t)Tc * DIMc];
__device__ float g_mo[(size_t)Tc * DIMc];
__device__ float g_hid[(size_t)Tc * HIDc];          // 134 MB expert hidden
__device__ float g_cos[Lc * 64];
__device__ float g_sin[Lc * 64];
__device__ int   g_ecnt[Ec];
__device__ int   g_etok[Ec * Tc];
__device__ float g_ewgt[Ec * Tc];

// ---------------- shared GEMM building blocks -------------------------------
__device__ __forceinline__ void load_a_tile(float (*As)[BM + 4],
                                            const float* Ab, int lda, int k0, int tid) {
#pragma unroll
    for (int i = 0; i < 2; i++) {
        int idx = tid + i * NTHR;           // 0..511
        int r = idx >> 2, c4 = (idx & 3) << 2;
        float4 a = *(const float4*)(Ab + (size_t)r * lda + k0 + c4);
        As[c4 + 0][r] = a.x; As[c4 + 1][r] = a.y;
        As[c4 + 2][r] = a.z; As[c4 + 3][r] = a.w;
    }
}

__device__ __forceinline__ void load_b_tile(float (*Bs)[BN + 4],
                                            const float* Bb, int ldb, int k0, int tid) {
#pragma unroll
    for (int i = 0; i < 2; i++) {
        int idx = tid + i * NTHR;
        int r = idx >> 5, c4 = (idx & 31) << 2;
        *(float4*)&Bs[r][c4] = *(const float4*)(Bb + (size_t)(k0 + r) * ldb + c4);
    }
}

__device__ __forceinline__ void mma_tile(const float (*As)[BM + 4],
                                         const float (*Bs)[BN + 4],
                                         float (&acc)[8][8], int ty, int tx) {
#pragma unroll
    for (int kk = 0; kk < BK; kk++) {
        float ra[8], rb[8];
#pragma unroll
        for (int i = 0; i < 8; i++) ra[i] = As[kk][ty * 8 + i];
#pragma unroll
        for (int j = 0; j < 8; j++) rb[j] = Bs[kk][tx * 8 + j];
#pragma unroll
        for (int i = 0; i < 8; i++)
#pragma unroll
            for (int j = 0; j < 8; j++)
                acc[i][j] = fmaf(ra[i], rb[j], acc[i][j]);
    }
}

// ---------------- elementwise / small kernels -------------------------------
__global__ void k_ropetab() {
    int idx = blockIdx.x * 256 + threadIdx.x;
    if (idx >= Lc * 64) return;
    int l = idx >> 6, i = idx & 63;
    double inv = exp(-((double)(2 * i) / (double)HDc) * log(10000.0));
    double f = (double)l * inv;
    g_cos[idx] = (float)cos(f);
    g_sin[idx] = (float)sin(f);
}

__global__ void k_zero() {
    size_t idx = (size_t)blockIdx.x * 256 + threadIdx.x;
    if (idx < (size_t)Tc * DIMc) g_mo[idx] = 0.f;
    if (idx < Ec) g_ecnt[idx] = 0;
}

__global__ void k_rmsnorm(const float* __restrict__ x, const float* __restrict__ w,
                          float* __restrict__ out) {
    int row = blockIdx.x, tid = threadIdx.x;
    const float* xr = x + (size_t)row * DIMc;
    __shared__ float red[256];
    float s = 0.f;
    for (int i = tid; i < DIMc; i += 256) { float v = xr[i]; s += v * v; }
    red[tid] = s; __syncthreads();
    for (int o = 128; o > 0; o >>= 1) {
        if (tid < o) red[tid] += red[tid + o];
        __syncthreads();
    }
    float inv = rsqrtf(red[0] * (1.f / DIMc) + 1e-6f);
    float* orow = out + (size_t)row * DIMc;
    for (int i = tid; i < DIMc; i += 256) orow[i] = xr[i] * inv * w[i];
}

__global__ void k_rope(float* __restrict__ p, int nheads) {
    int idx = blockIdx.x * 256 + threadIdx.x;
    int tot = Tc * nheads * 64;
    if (idx >= tot) return;
    int d = idx & 63;
    int rest = idx >> 6;
    int h = rest % nheads;
    int t = rest / nheads;
    int l = t & (Lc - 1);
    float c = g_cos[l * 64 + d], s = g_sin[l * 64 + d];
    float* base = p + (size_t)t * (nheads * HDc) + h * HDc;
    float x1 = base[d], x2 = base[d + 64];
    base[d]      = x1 * c - x2 * s;
    base[d + 64] = x2 * c + x1 * s;
}

__global__ void k_add(const float* __restrict__ x) {
    size_t idx = (size_t)blockIdx.x * 256 + threadIdx.x;
    if (idx < (size_t)Tc * DIMc) g_h[idx] = x[idx] + g_q[idx];   // g_q holds o-proj
}

__global__ void k_final(float* __restrict__ out) {
    size_t idx = (size_t)blockIdx.x * 256 + threadIdx.x;
    if (idx < (size_t)Tc * DIMc) out[idx] = g_h[idx] + g_mo[idx];
}

// ---------------- dense GEMM ------------------------------------------------
__global__ __launch_bounds__(NTHR) void k_gemm_nn(const float* __restrict__ A,
                                                  const float* __restrict__ B,
                                                  float* __restrict__ C,
                                                  int K, int lda, int ldb, int ldc) {
    __shared__ float As[BK][BM + 4];
    __shared__ float Bs[BK][BN + 4];
    int tid = threadIdx.x, tx = tid & 15, ty = tid >> 4;
    const float* Ab = A + (size_t)blockIdx.y * BM * lda;
    const float* Bb = B + (size_t)blockIdx.x * BN;
    float acc[8][8] = {};
    for (int k0 = 0; k0 < K; k0 += BK) {
        load_a_tile(As, Ab, lda, k0, tid);
        load_b_tile(Bs, Bb, ldb, k0, tid);
        __syncthreads();
        mma_tile(As, Bs, acc, ty, tx);
        __syncthreads();
    }
    float* Cb = C + (size_t)(blockIdx.y * BM + ty * 8) * ldc + blockIdx.x * BN + tx * 8;
#pragma unroll
    for (int i = 0; i < 8; i++) {
        *(float4*)(Cb + (size_t)i * ldc)     = make_float4(acc[i][0], acc[i][1], acc[i][2], acc[i][3]);
        *(float4*)(Cb + (size_t)i * ldc + 4) = make_float4(acc[i][4], acc[i][5], acc[i][6], acc[i][7]);
    }
}

// ---------------- fused causal flash attention ------------------------------
// grid: (1, Lc/FA_BQ, B*H); block: 256 (16x16); dynamic smem ~80 KB
// Each thread owns 8 q-rows (ty*8..) and 8 O-cols (tx*8..); S tile cols tx*4..
__global__ __launch_bounds__(NTHR) void k_flash() {
    extern __shared__ float sm[];
    float (*Qs)[FA_BQ + 4] = (float(*)[FA_BQ + 4])sm;                          // [16][132]
    float (*Ks)[FA_BK + 4] = (float(*)[FA_BK + 4])(sm + 16 * (FA_BQ + 4));     // [16][68]
    float (*Ps)[FA_BQ + 4] = (float(*)[FA_BQ + 4])(sm + 16 * (FA_BQ + 4) + 16 * (FA_BK + 4));  // [64][132]
    float (*Vs)[HDc  + 4]  = (float(*)[HDc + 4]) (sm + 16 * (FA_BQ + 4) + 16 * (FA_BK + 4)
                                                     + 64 * (FA_BQ + 4));      // [64][132]
    int by = blockIdx.y, bz = blockIdx.z;
    int b = bz / Hc, h = bz % Hc, kh = h / (Hc / KVHc);
    int tid = threadIdx.x, tx = tid & 15, ty = tid >> 4;

    const float* Qb = g_q + (size_t)(b * Lc + by * FA_BQ) * DIMc + h * HDc;

    float accO[8][8] = {};
    float m[8], l[8];
#pragma unroll
    for (int i = 0; i < 8; i++) { m[i] = -1e30f; l[i] = 0.f; }

    int qrow0 = by * FA_BQ + ty * 8;
    const int jend = (by + 1) * (FA_BQ / FA_BK);

    for (int j = 0; j < jend; j++) {
        const float* Kb = g_k + (size_t)(b * Lc + j * FA_BK) * KVDc + kh * HDc;
        // ---- S = Q @ K^T over HD=128 --------------------------------------
        float accS[8][4] = {};
#pragma unroll
        for (int k0 = 0; k0 < HDc; k0 += BK) {
#pragma unroll
            for (int i = 0; i < 2; i++) {            // Q tile: 128 rows x 16
                int idx = tid + i * NTHR;
                int r = idx >> 2, c4 = (idx & 3) << 2;
                float4 a = *(const float4*)(Qb + (size_t)r * DIMc + k0 + c4);
                Qs[c4 + 0][r] = a.x; Qs[c4 + 1][r] = a.y;
                Qs[c4 + 2][r] = a.z; Qs[c4 + 3][r] = a.w;
            }
            {                                         // K tile: 64 rows x 16 (transposed)
                int r = tid >> 2, c4 = (tid & 3) << 2;
                float4 bv = *(const float4*)(Kb + (size_t)r * KVDc + k0 + c4);
                Ks[c4 + 0][r] = bv.x; Ks[c4 + 1][r] = bv.y;
                Ks[c4 + 2][r] = bv.z; Ks[c4 + 3][r] = bv.w;
            }
            __syncthreads();
#pragma unroll
            for (int kk = 0; kk < BK; kk++) {
                float ra[8], rb[4];
#pragma unroll
                for (int i = 0; i < 8; i++) ra[i] = Qs[kk][ty * 8 + i];
#pragma unroll
                for (int j2 = 0; j2 < 4; j2++) rb[j2] = Ks[kk][tx * 4 + j2];
#pragma unroll
                for (int i = 0; i < 8; i++)
#pragma unroll
                    for (int j2 = 0; j2 < 4; j2++)
                        accS[i][j2] = fmaf(ra[i], rb[j2], accS[i][j2]);
            }
            __syncthreads();
        }
        // ---- scale + causal mask + online softmax -------------------------
        const float scale = 0.08838834764831843f;    // 1/sqrt(128)
        int kcol0 = j * FA_BK + tx * 4;
        float rmax[8];
#pragma unroll
        for (int i = 0; i < 8; i++) {
            float mx = -1e30f;
#pragma unroll
            for (int j2 = 0; j2 < 4; j2++) {
                float v = (kcol0 + j2 <= qrow0 + i) ? accS[i][j2] * scale : -1e30f;
                accS[i][j2] = v;
                mx = fmaxf(mx, v);
            }
            rmax[i] = mx;
        }
#pragma unroll
        for (int off = 8; off > 0; off >>= 1)
#pragma unroll
            for (int i = 0; i < 8; i++)
                rmax[i] = fmaxf(rmax[i], __shfl_xor_sync(0xffffffffu, rmax[i], off, 16));
        float rsum[8];
#pragma unroll
        for (int i = 0; i < 8; i++) {
            float mn = fmaxf(m[i], rmax[i]);
            float alpha = __expf(m[i] - mn);
            m[i] = mn;
            float s = 0.f;
#pragma unroll
            for (int j2 = 0; j2 < 4; j2++) {
                float p = __expf(accS[i][j2] - mn);
                accS[i][j2] = p;
                s += p;
            }
            rsum[i] = s;
            l[i] *= alpha;
#pragma unroll
            for (int jj = 0; jj < 8; jj++) accO[i][jj] *= alpha;
        }
#pragma unroll
        for (int off = 8; off > 0; off >>= 1)
#pragma unroll
            for (int i = 0; i < 8; i++)
                rsum[i] += __shfl_xor_sync(0xffffffffu, rsum[i], off, 16);
#pragma unroll
        for (int i = 0; i < 8; i++) l[i] += rsum[i];

        // ---- stage P (transposed) and V, then O += P @ V ------------------
#pragma unroll
        for (int i = 0; i < 8; i++)
#pragma unroll
            for (int j2 = 0; j2 < 4; j2++)
                Ps[tx * 4 + j2][ty * 8 + i] = accS[i][j2];
        const float* Vb = g_v + (size_t)(b * Lc + j * FA_BK) * KVDc + kh * HDc;
#pragma unroll
        for (int i = 0; i < 8; i++) {                // V tile: 64 rows x 128
            int idx = tid + i * NTHR;
            int r = idx >> 5, c4 = (idx & 31) << 2;
            *(float4*)&Vs[r][c4] = *(const float4*)(Vb + (size_t)r * KVDc + c4);
        }
        __syncthreads();
#pragma unroll
        for (int kk = 0; kk < FA_BK; kk++) {
            float ra[8], rb[8];
#pragma unroll
            for (int i = 0; i < 8; i++) ra[i] = Ps[kk][ty * 8 + i];
#pragma unroll
            for (int jj = 0; jj < 8; jj++) rb[jj] = Vs[kk][tx * 8 + jj];
#pragma unroll
            for (int i = 0; i < 8; i++)
#pragma unroll
                for (int jj = 0; jj < 8; jj++)
                    accO[i][jj] = fmaf(ra[i], rb[jj], accO[i][jj]);
        }
        __syncthreads();
    }
    // ---- epilogue: O / l -> g_ao -----------------------------------------
#pragma unroll
    for (int i = 0; i < 8; i++) {
        float inv = 1.f / l[i];
        float* dst = g_ao + (size_t)(b * Lc + qrow0 + i) * DIMc + h * HDc + tx * 8;
        *(float4*)(dst)     = make_float4(accO[i][0] * inv, accO[i][1] * inv,
                                          accO[i][2] * inv, accO[i][3] * inv);
        *(float4*)(dst + 4) = make_float4(accO[i][4] * inv, accO[i][5] * inv,
                                          accO[i][6] * inv, accO[i][7] * inv);
    }
}

// ---------------- router + MoE ----------------------------------------------
__global__ void k_router(const float* __restrict__ rw) {
    int t = blockIdx.x, tid = threadIdx.x;
    __shared__ float red[8][257];
    const float* xr = g_hn + (size_t)t * DIMc;
    float acc[8] = {};
    for (int i = tid; i < DIMc; i += 256) {
        float xv = xr[i];
#pragma unroll
        for (int e = 0; e < 8; e++) acc[e] += xv * rw[i * Ec + e];
    }
#pragma unroll
    for (int e = 0; e < 8; e++) red[e][tid] = acc[e];
    __syncthreads();
    for (int o = 128; o > 0; o >>= 1) {
        if (tid < o) {
#pragma unroll
            for (int e = 0; e < 8; e++) red[e][tid] += red[e][tid + o];
        }
        __syncthreads();
    }
    if (tid == 0) {
        float lg[8];
#pragma unroll
        for (int e = 0; e < 8; e++) lg[e] = red[e][0];
        int i0 = 0;
        for (int e = 1; e < 8; e++) if (lg[e] > lg[i0]) i0 = e;
        int i1 = (i0 == 0) ? 1 : 0;
        for (int e = 0; e < 8; e++) { if (e == i0) continue; if (lg[e] > lg[i1]) i1 = e; }
        // softmax over all 8 then renormalize top-2 == pairwise sigmoid
        float w0 = 1.f / (1.f + expf(lg[i1] - lg[i0]));
        float w1 = 1.f - w0;
        int s0 = atomicAdd(&g_ecnt[i0], 1);
        g_etok[i0 * Tc + s0] = t; g_ewgt[i0 * Tc + s0] = w0;
        int s1 = atomicAdd(&g_ecnt[i1], 1);
        g_etok[i1 * Tc + s1] = t; g_ewgt[i1 * Tc + s1] = w1;
    }
}

// hid[i] = silu(hn[tok[i]] @ w1[e]) — gathered rows, store-guarded on count
__global__ __launch_bounds__(NTHR) void k_moe1(const float* __restrict__ W, int e) {
    int cnt = g_ecnt[e];
    int by = blockIdx.y;
    if (by * BM >= cnt) return;
    __shared__ int toks[BM];
    __shared__ float As[BK][BM + 4];
    __shared__ float Bs[BK][BN + 4];
    int tid = threadIdx.x, tx = tid & 15, ty = tid >> 4;
    if (tid < BM) {
        int r = by * BM + tid;
        toks[tid] = g_etok[e * Tc + (r < cnt ? r : cnt - 1)];
    }
    __syncthreads();
    const float* Bb = W + (size_t)blockIdx.x * BN;
    float acc[8][8] = {};
    for (int k0 = 0; k0 < DIMc; k0 += BK) {
#pragma unroll
        for (int i = 0; i < 2; i++) {                // gathered A tile
            int idx = tid + i * NTHR;
            int r = idx >> 2, c4 = (idx & 3) << 2;
            const float* arow = g_hn + (size_t)toks[r] * DIMc;
            float4 a = *(const float4*)(arow + k0 + c4);
            As[c4 + 0][r] = a.x; As[c4 + 1][r] = a.y;
            As[c4 + 2][r] = a.z; As[c4 + 3][r] = a.w;
        }
        load_b_tile(Bs, Bb, HIDc, k0, tid);
        __syncthreads();
        mma_tile(As, Bs, acc, ty, tx);
        __syncthreads();
    }
#pragma unroll
    for (int i = 0; i < 8; i++) {
        int r = by * BM + ty * 8 + i;
        if (r >= cnt) continue;
        float* dst = g_hid + (size_t)r * HIDc + blockIdx.x * BN + tx * 8;
#pragma unroll
        for (int j = 0; j < 8; j++) {
            float v = acc[i][j];
            dst[j] = v / (1.f + expf(-v));           // silu
        }
    }
}

// moe_out[tok[i]] += w[i] * (hid[i] @ w2[e]) — scatter, sequential per expert
__global__ __launch_bounds__(NTHR) void k_moe2(const float* __restrict__ W, int e) {
    int cnt = g_ecnt[e];
    int by = blockIdx.y;
    if (by * BM >= cnt) return;
    __shared__ int toks[BM];
    __shared__ float wr[BM];
    __shared__ float As[BK][BM + 4];
    __shared__ float Bs[BK][BN + 4];
    int tid = threadIdx.x, tx = tid & 15, ty = tid >> 4;
    if (tid < BM) {
        int r = by * BM + tid;
        int rc = (r < cnt ? r : cnt - 1);
        toks[tid] = g_etok[e * Tc + rc];
        wr[tid]   = g_ewgt[e * Tc + rc];
    }
    __syncthreads();
    const float* Ab = g_hid + (size_t)by * BM * HIDc;
    const float* Bb = W + (size_t)blockIdx.x * BN;
    float acc[8][8] = {};
    for (int k0 = 0; k0 < HIDc; k0 += BK) {
        load_a_tile(As, Ab, HIDc, k0, tid);
        load_b_tile(Bs, Bb, DIMc, k0, tid);
        __syncthreads();
        mma_tile(As, Bs, acc, ty, tx);
        __syncthreads();
    }
#pragma unroll
    for (int i = 0; i < 8; i++) {
        int lr = ty * 8 + i;
        int r = by * BM + lr;
        if (r >= cnt) continue;
        float w = wr[lr];
        float* dst = g_mo + (size_t)toks[lr] * DIMc + blockIdx.x * BN + tx * 8;
#pragma unroll
        for (int j = 0; j < 8; j++) dst[j] += w * acc[i][j];
    }
}

// ---------------- launch ----------------------------------------------------
extern "C" void kernel_launch(void* const* d_in, const int* in_sizes, int n_in,
                              void* d_out, int out_size) {
    const float* x   = (const float*)d_in[0];
    const float* n1w = (const float*)d_in[1];
    const float* wq  = (const float*)d_in[2];
    const float* wk  = (const float*)d_in[3];
    const float* wv  = (const float*)d_in[4];
    const float* wo  = (const float*)d_in[5];
    const float* n2w = (const float*)d_in[6];
    const float* rw  = (const float*)d_in[7];
    const float* w1  = (const float*)d_in[8];
    const float* w2  = (const float*)d_in[9];
    float* out = (float*)d_out;

    float *p_xn, *p_q, *p_k, *p_v, *p_ao, *p_h, *p_hn;
    cudaGetSymbolAddress((void**)&p_xn, g_xn);
    cudaGetSymbolAddress((void**)&p_q,  g_q);
    cudaGetSymbolAddress((void**)&p_k,  g_k);
    cudaGetSymbolAddress((void**)&p_v,  g_v);
    cudaGetSymbolAddress((void**)&p_ao, g_ao);
    cudaGetSymbolAddress((void**)&p_h,  g_h);
    cudaGetSymbolAddress((void**)&p_hn, g_hn);

    // flash-attention dynamic smem: Qs + Ks + Ps + Vs
    const int FA_SMEM = (16 * (FA_BQ + 4) + 16 * (FA_BK + 4) +
                         64 * (FA_BQ + 4) + 64 * (HDc + 4)) * (int)sizeof(float);
    static int attr_done = 0;
    if (!attr_done) {
        cudaFuncSetAttribute(k_flash, cudaFuncAttributeMaxDynamicSharedMemorySize, FA_SMEM);
        attr_done = 1;
    }

    dim3 blk(NTHR);
    const int EW = (Tc * DIMc + 255) / 256;

    k_ropetab<<<(Lc * 64 + 255) / 256, 256>>>();
    k_zero<<<EW, 256>>>();

    // rmsnorm1 + QKV projections
    k_rmsnorm<<<Tc, 256>>>(x, n1w, p_xn);
    k_gemm_nn<<<dim3(DIMc / BN, Tc / BM), blk>>>(p_xn, wq, p_q, DIMc, DIMc, DIMc, DIMc);
    k_gemm_nn<<<dim3(KVDc / BN, Tc / BM), blk>>>(p_xn, wk, p_k, DIMc, DIMc, KVDc, KVDc);
    k_gemm_nn<<<dim3(KVDc / BN, Tc / BM), blk>>>(p_xn, wv, p_v, DIMc, DIMc, KVDc, KVDc);

    // RoPE
    k_rope<<<(Tc * Hc * 64 + 255) / 256, 256>>>(p_q, Hc);
    k_rope<<<(Tc * KVHc * 64 + 255) / 256, 256>>>(p_k, KVHc);

    // fused causal attention
    k_flash<<<dim3(1, Lc / FA_BQ, Bc * Hc), blk, FA_SMEM>>>();

    // o-proj (into g_q, reused) + residual + rmsnorm2
    k_gemm_nn<<<dim3(DIMc / BN, Tc / BM), blk>>>(p_ao, wo, p_q, DIMc, DIMc, DIMc, DIMc);
    k_add<<<EW, 256>>>(x);
    k_rmsnorm<<<Tc, 256>>>(p_h, n2w, p_hn);

    // MoE
    k_router<<<Tc, 256>>>(rw);
    for (int e = 0; e < Ec; e++) {
        k_moe1<<<dim3(HIDc / BN, Tc / BM), blk>>>(w1 + (size_t)e * DIMc * HIDc, e);
        k_moe2<<<dim3(DIMc / BN, Tc / BM), blk>>>(w2 + (size_t)e * HIDc * DIMc, e);
    }

    k_final<<<EW, 256>>>(out);
}

// round 8
// speedup vs baseline: 1.5688x; 1.5688x over previous
#include <cuda_runtime.h>
#include <cuda_bf16.h>
#include <mma.h>
#include <math.h>

using namespace nvcuda;

typedef unsigned int   u32;
typedef unsigned short u16;

#define Bc 2
#define Lc 2048
#define Tc 4096
#define DIMc 2048
#define Hc 16
#define KVHc 4
#define HDc 128
#define Ec 8
#define HIDc 8192
#define KVDc 512

#define NTHR 256

// flash-attention tiling
#define FA_BQ 128
#define FA_BK 64

// bf16x3 GEMM tiling
#define GBM 128
#define GBN 128
#define GBK 32
#define A_LD 40      // GBK + 8 pad (bf16 elems) -> 80B rows, 16B aligned, ldm%8==0
#define B_LD 136     // GBN + 8 pad (bf16 elems) -> 272B rows, 16B aligned, ldm%8==0

// ---------------- scratch (device globals; no allocations allowed) ----------
__device__ float g_xn[(size_t)Tc * DIMc];
__device__ float g_q [(size_t)Tc * DIMc];
__device__ float g_k [(size_t)Tc * KVDc];
__device__ float g_v [(size_t)Tc * KVDc];
__device__ float g_ao[(size_t)Tc * DIMc];
__device__ float g_h [(size_t)Tc * DIMc];
__device__ float g_hn[(size_t)Tc * DIMc];
__device__ float g_mo[(size_t)Tc * DIMc];
__device__ u16   g_hid_h[(size_t)Tc * HIDc];   // expert hidden, hi bf16 bits
__device__ u16   g_hid_l[(size_t)Tc * HIDc];   // expert hidden, lo bf16 bits
__device__ float g_cos[Lc * 64];
__device__ float g_sin[Lc * 64];
__device__ int   g_ecnt[Ec];
__device__ int   g_etok[Ec * Tc];
__device__ float g_ewgt[Ec * Tc];

// ---------------- bf16 bit helpers ------------------------------------------
__device__ __forceinline__ u32 f2b(float f) {          // float -> bf16 bits (RNE)
    u32 u = __float_as_uint(f);
    return (u + 0x7FFFu + ((u >> 16) & 1u)) >> 16;
}
__device__ __forceinline__ float b2f(u32 b) {          // bf16 bits -> float
    return __uint_as_float(b << 16);
}

// split float4 into hi/lo bf16 pairs; store 8B to each tile
__device__ __forceinline__ void split_store(u16* dh, u16* dl, float4 v) {
    u32 h0 = f2b(v.x), h1 = f2b(v.y), h2 = f2b(v.z), h3 = f2b(v.w);
    u32 l0 = f2b(v.x - b2f(h0));
    u32 l1 = f2b(v.y - b2f(h1));
    u32 l2 = f2b(v.z - b2f(h2));
    u32 l3 = f2b(v.w - b2f(h3));
    uint2 hw; hw.x = h0 | (h1 << 16); hw.y = h2 | (h3 << 16);
    uint2 lw; lw.x = l0 | (l1 << 16); lw.y = l2 | (l3 << 16);
    *reinterpret_cast<uint2*>(dh) = hw;
    *reinterpret_cast<uint2*>(dl) = lw;
}

typedef wmma::fragment<wmma::accumulator, 16, 16, 16, float> AccFrag;
typedef wmma::fragment<wmma::matrix_a, 16, 16, 16, __nv_bfloat16, wmma::row_major> AFrag;
typedef wmma::fragment<wmma::matrix_b, 16, 16, 16, __nv_bfloat16, wmma::row_major> BFrag;

// A tile staging: fp32 gmem [row, k contiguous] -> hi/lo bf16 smem [128][A_LD]
__device__ __forceinline__ void stage_a(u16* Ah, u16* Al,
                                        const float* Ab, int lda, int k0, int tid) {
#pragma unroll
    for (int i = 0; i < 4; i++) {
        int idx = tid + i * NTHR;                  // 0..1023
        int r = idx >> 3, c4 = (idx & 7) << 2;     // 128 rows x 8 float4
        float4 v = *(const float4*)(Ab + (size_t)r * lda + k0 + c4);
        split_store(Ah + r * A_LD + c4, Al + r * A_LD + c4, v);
    }
}

// B tile staging: fp32 gmem [K,N] -> hi/lo bf16 smem [GBK][B_LD]
__device__ __forceinline__ void stage_b(u16* Bh, u16* Bl,
                                        const float* Bb, int ldb, int k0, int tid) {
#pragma unroll
    for (int i = 0; i < 4; i++) {
        int idx = tid + i * NTHR;
        int kr = idx >> 5, nc = (idx & 31) << 2;   // 32 rows x 32 float4
        float4 v = *(const float4*)(Bb + (size_t)(k0 + kr) * ldb + nc);
        split_store(Bh + kr * B_LD + nc, Bl + kr * B_LD + nc, v);
    }
}

// one 128x128x32 chunk of bf16x3 WMMAs (warp tile 64x32; 8 warps 2x4)
__device__ __forceinline__ void wmma_chunk(const u16* Ah, const u16* Al,
                                           const u16* Bh, const u16* Bl,
                                           AccFrag (&acc)[4][2], int wm, int wn) {
    int m_off = wm * 64, n_off = wn * 32;
#pragma unroll
    for (int kk = 0; kk < GBK; kk += 16) {
        BFrag bh[2], bl[2];
#pragma unroll
        for (int nb = 0; nb < 2; nb++) {
            wmma::load_matrix_sync(bh[nb],
                (const __nv_bfloat16*)(Bh + kk * B_LD + n_off + nb * 16), B_LD);
            wmma::load_matrix_sync(bl[nb],
                (const __nv_bfloat16*)(Bl + kk * B_LD + n_off + nb * 16), B_LD);
        }
#pragma unroll
        for (int mb = 0; mb < 4; mb++) {
            AFrag ah, al;
            wmma::load_matrix_sync(ah,
                (const __nv_bfloat16*)(Ah + (m_off + mb * 16) * A_LD + kk), A_LD);
            wmma::load_matrix_sync(al,
                (const __nv_bfloat16*)(Al + (m_off + mb * 16) * A_LD + kk), A_LD);
#pragma unroll
            for (int nb = 0; nb < 2; nb++) {
                wmma::mma_sync(acc[mb][nb], ah, bh[nb], acc[mb][nb]);
                wmma::mma_sync(acc[mb][nb], ah, bl[nb], acc[mb][nb]);
                wmma::mma_sync(acc[mb][nb], al, bh[nb], acc[mb][nb]);
            }
        }
    }
}

// ---------------- dense bf16x3 GEMM: C = A @ B ------------------------------
__global__ __launch_bounds__(NTHR) void k_gemm_bf3(const float* __restrict__ A,
                                                   const float* __restrict__ B,
                                                   float* __restrict__ C,
                                                   int K, int lda, int ldb, int ldc) {
    __shared__ __align__(16) u16 Ah[GBM * A_LD], Al[GBM * A_LD];
    __shared__ __align__(16) u16 Bh[GBK * B_LD], Bl[GBK * B_LD];
    int tid = threadIdx.x, wid = tid >> 5;
    int wm = wid >> 2, wn = wid & 3;
    const float* Ab = A + (size_t)blockIdx.y * GBM * lda;
    const float* Bb = B + (size_t)blockIdx.x * GBN;
    AccFrag acc[4][2];
#pragma unroll
    for (int mb = 0; mb < 4; mb++)
#pragma unroll
        for (int nb = 0; nb < 2; nb++) wmma::fill_fragment(acc[mb][nb], 0.f);
    for (int k0 = 0; k0 < K; k0 += GBK) {
        stage_a(Ah, Al, Ab, lda, k0, tid);
        stage_b(Bh, Bl, Bb, ldb, k0, tid);
        __syncthreads();
        wmma_chunk(Ah, Al, Bh, Bl, acc, wm, wn);
        __syncthreads();
    }
#pragma unroll
    for (int mb = 0; mb < 4; mb++)
#pragma unroll
        for (int nb = 0; nb < 2; nb++) {
            int row = blockIdx.y * GBM + wm * 64 + mb * 16;
            int col = blockIdx.x * GBN + wn * 32 + nb * 16;
            wmma::store_matrix_sync(C + (size_t)row * ldc + col, acc[mb][nb],
                                    ldc, wmma::mem_row_major);
        }
}

// ---------------- elementwise / small kernels -------------------------------
__global__ void k_ropetab() {
    int idx = blockIdx.x * 256 + threadIdx.x;
    if (idx >= Lc * 64) return;
    int l = idx >> 6, i = idx & 63;
    double inv = exp(-((double)(2 * i) / (double)HDc) * log(10000.0));
    double f = (double)l * inv;
    g_cos[idx] = (float)cos(f);
    g_sin[idx] = (float)sin(f);
}

__global__ void k_zero() {
    size_t idx = (size_t)blockIdx.x * 256 + threadIdx.x;
    if (idx < (size_t)Tc * DIMc) g_mo[idx] = 0.f;
    if (idx < Ec) g_ecnt[idx] = 0;
}

__global__ void k_rmsnorm(const float* __restrict__ x, const float* __restrict__ w,
                          float* __restrict__ out) {
    int row = blockIdx.x, tid = threadIdx.x;
    const float* xr = x + (size_t)row * DIMc;
    __shared__ float red[256];
    float s = 0.f;
    for (int i = tid; i < DIMc; i += 256) { float v = xr[i]; s += v * v; }
    red[tid] = s; __syncthreads();
    for (int o = 128; o > 0; o >>= 1) {
        if (tid < o) red[tid] += red[tid + o];
        __syncthreads();
    }
    float inv = rsqrtf(red[0] * (1.f / DIMc) + 1e-6f);
    float* orow = out + (size_t)row * DIMc;
    for (int i = tid; i < DIMc; i += 256) orow[i] = xr[i] * inv * w[i];
}

__global__ void k_rope(float* __restrict__ p, int nheads) {
    int idx = blockIdx.x * 256 + threadIdx.x;
    int tot = Tc * nheads * 64;
    if (idx >= tot) return;
    int d = idx & 63;
    int rest = idx >> 6;
    int h = rest % nheads;
    int t = rest / nheads;
    int l = t & (Lc - 1);
    float cv = g_cos[l * 64 + d], sv = g_sin[l * 64 + d];
    float* base = p + (size_t)t * (nheads * HDc) + h * HDc;
    float x1 = base[d], x2 = base[d + 64];
    base[d]      = x1 * cv - x2 * sv;
    base[d + 64] = x2 * cv + x1 * sv;
}

__global__ void k_add(const float* __restrict__ x) {
    size_t idx = (size_t)blockIdx.x * 256 + threadIdx.x;
    if (idx < (size_t)Tc * DIMc) g_h[idx] = x[idx] + g_q[idx];   // g_q holds o-proj
}

__global__ void k_final(float* __restrict__ out) {
    size_t idx = (size_t)blockIdx.x * 256 + threadIdx.x;
    if (idx < (size_t)Tc * DIMc) out[idx] = g_h[idx] + g_mo[idx];
}

// ---------------- fused causal flash attention (fp32) -----------------------
__global__ __launch_bounds__(NTHR) void k_flash() {
    extern __shared__ float sm[];
    float (*Qs)[FA_BQ + 4] = (float(*)[FA_BQ + 4])sm;
    float (*Ks)[FA_BK + 4] = (float(*)[FA_BK + 4])(sm + 16 * (FA_BQ + 4));
    float (*Ps)[FA_BQ + 4] = (float(*)[FA_BQ + 4])(sm + 16 * (FA_BQ + 4) + 16 * (FA_BK + 4));
    float (*Vs)[HDc  + 4]  = (float(*)[HDc + 4]) (sm + 16 * (FA_BQ + 4) + 16 * (FA_BK + 4)
                                                     + 64 * (FA_BQ + 4));
    int by = blockIdx.y, bz = blockIdx.z;
    int b = bz / Hc, h = bz % Hc, kh = h / (Hc / KVHc);
    int tid = threadIdx.x, tx = tid & 15, ty = tid >> 4;

    const float* Qb = g_q + (size_t)(b * Lc + by * FA_BQ) * DIMc + h * HDc;

    float accO[8][8] = {};
    float m[8], l[8];
#pragma unroll
    for (int i = 0; i < 8; i++) { m[i] = -1e30f; l[i] = 0.f; }

    int qrow0 = by * FA_BQ + ty * 8;
    const int jend = (by + 1) * (FA_BQ / FA_BK);

    for (int j = 0; j < jend; j++) {
        const float* Kb = g_k + (size_t)(b * Lc + j * FA_BK) * KVDc + kh * HDc;
        float accS[8][4] = {};
#pragma unroll
        for (int k0 = 0; k0 < HDc; k0 += 16) {
#pragma unroll
            for (int i = 0; i < 2; i++) {
                int idx = tid + i * NTHR;
                int r = idx >> 2, c4 = (idx & 3) << 2;
                float4 a = *(const float4*)(Qb + (size_t)r * DIMc + k0 + c4);
                Qs[c4 + 0][r] = a.x; Qs[c4 + 1][r] = a.y;
                Qs[c4 + 2][r] = a.z; Qs[c4 + 3][r] = a.w;
            }
            {
                int r = tid >> 2, c4 = (tid & 3) << 2;
                float4 bv = *(const float4*)(Kb + (size_t)r * KVDc + k0 + c4);
                Ks[c4 + 0][r] = bv.x; Ks[c4 + 1][r] = bv.y;
                Ks[c4 + 2][r] = bv.z; Ks[c4 + 3][r] = bv.w;
            }
            __syncthreads();
#pragma unroll
            for (int kk = 0; kk < 16; kk++) {
                float ra[8], rb[4];
#pragma unroll
                for (int i = 0; i < 8; i++) ra[i] = Qs[kk][ty * 8 + i];
#pragma unroll
                for (int j2 = 0; j2 < 4; j2++) rb[j2] = Ks[kk][tx * 4 + j2];
#pragma unroll
                for (int i = 0; i < 8; i++)
#pragma unroll
                    for (int j2 = 0; j2 < 4; j2++)
                        accS[i][j2] = fmaf(ra[i], rb[j2], accS[i][j2]);
            }
            __syncthreads();
        }
        const float scale = 0.08838834764831843f;
        int kcol0 = j * FA_BK + tx * 4;
        float rmax[8];
#pragma unroll
        for (int i = 0; i < 8; i++) {
            float mx = -1e30f;
#pragma unroll
            for (int j2 = 0; j2 < 4; j2++) {
                float v = (kcol0 + j2 <= qrow0 + i) ? accS[i][j2] * scale : -1e30f;
                accS[i][j2] = v;
                mx = fmaxf(mx, v);
            }
            rmax[i] = mx;
        }
#pragma unroll
        for (int off = 8; off > 0; off >>= 1)
#pragma unroll
            for (int i = 0; i < 8; i++)
                rmax[i] = fmaxf(rmax[i], __shfl_xor_sync(0xffffffffu, rmax[i], off, 16));
        float rsum[8];
#pragma unroll
        for (int i = 0; i < 8; i++) {
            float mn = fmaxf(m[i], rmax[i]);
            float alpha = __expf(m[i] - mn);
            m[i] = mn;
            float s = 0.f;
#pragma unroll
            for (int j2 = 0; j2 < 4; j2++) {
                float pv = __expf(accS[i][j2] - mn);
                accS[i][j2] = pv;
                s += pv;
            }
            rsum[i] = s;
            l[i] *= alpha;
#pragma unroll
            for (int jj = 0; jj < 8; jj++) accO[i][jj] *= alpha;
        }
#pragma unroll
        for (int off = 8; off > 0; off >>= 1)
#pragma unroll
            for (int i = 0; i < 8; i++)
                rsum[i] += __shfl_xor_sync(0xffffffffu, rsum[i], off, 16);
#pragma unroll
        for (int i = 0; i < 8; i++) l[i] += rsum[i];

#pragma unroll
        for (int i = 0; i < 8; i++)
#pragma unroll
            for (int j2 = 0; j2 < 4; j2++)
                Ps[tx * 4 + j2][ty * 8 + i] = accS[i][j2];
        const float* Vb = g_v + (size_t)(b * Lc + j * FA_BK) * KVDc + kh * HDc;
#pragma unroll
        for (int i = 0; i < 8; i++) {
            int idx = tid + i * NTHR;
            int r = idx >> 5, c4 = (idx & 31) << 2;
            *(float4*)&Vs[r][c4] = *(const float4*)(Vb + (size_t)r * KVDc + c4);
        }
        __syncthreads();
#pragma unroll
        for (int kk = 0; kk < FA_BK; kk++) {
            float ra[8], rb[8];
#pragma unroll
            for (int i = 0; i < 8; i++) ra[i] = Ps[kk][ty * 8 + i];
#pragma unroll
            for (int jj = 0; jj < 8; jj++) rb[jj] = Vs[kk][tx * 8 + jj];
#pragma unroll
            for (int i = 0; i < 8; i++)
#pragma unroll
                for (int jj = 0; jj < 8; jj++)
                    accO[i][jj] = fmaf(ra[i], rb[jj], accO[i][jj]);
        }
        __syncthreads();
    }
#pragma unroll
    for (int i = 0; i < 8; i++) {
        float inv = 1.f / l[i];
        float* dst = g_ao + (size_t)(b * Lc + qrow0 + i) * DIMc + h * HDc + tx * 8;
        float4 o0; o0.x = accO[i][0] * inv; o0.y = accO[i][1] * inv;
        o0.z = accO[i][2] * inv; o0.w = accO[i][3] * inv;
        float4 o1; o1.x = accO[i][4] * inv; o1.y = accO[i][5] * inv;
        o1.z = accO[i][6] * inv; o1.w = accO[i][7] * inv;
        *(float4*)(dst)     = o0;
        *(float4*)(dst + 4) = o1;
    }
}

// ---------------- router ----------------------------------------------------
__global__ void k_router(const float* __restrict__ rw) {
    int tok = blockIdx.x, tid = threadIdx.x;
    __shared__ float red[8][257];
    const float* xr = g_hn + (size_t)tok * DIMc;
    float acc[8] = {};
    for (int i = tid; i < DIMc; i += 256) {
        float xv = xr[i];
#pragma unroll
        for (int e = 0; e < 8; e++) acc[e] += xv * rw[i * Ec + e];
    }
#pragma unroll
    for (int e = 0; e < 8; e++) red[e][tid] = acc[e];
    __syncthreads();
    for (int o = 128; o > 0; o >>= 1) {
        if (tid < o) {
#pragma unroll
            for (int e = 0; e < 8; e++) red[e][tid] += red[e][tid + o];
        }
        __syncthreads();
    }
    if (tid == 0) {
        float lgts[8];
#pragma unroll
        for (int e = 0; e < 8; e++) lgts[e] = red[e][0];
        int bestA = 0;
        for (int e = 1; e < 8; e++) { if (lgts[e] > lgts[bestA]) bestA = e; }
        int bestB = (bestA == 0) ? 1 : 0;
        for (int e = 0; e < 8; e++) {
            if (e == bestA) continue;
            if (lgts[e] > lgts[bestB]) bestB = e;
        }
        // softmax over 8 then renormalize top-2 == pairwise sigmoid
        float wtA = 1.f / (1.f + expf(lgts[bestB] - lgts[bestA]));
        float wtB = 1.f - wtA;
        int slotA = atomicAdd(&g_ecnt[bestA], 1);
        g_etok[bestA * Tc + slotA] = tok;
        g_ewgt[bestA * Tc + slotA] = wtA;
        int slotB = atomicAdd(&g_ecnt[bestB], 1);
        g_etok[bestB * Tc + slotB] = tok;
        g_ewgt[bestB * Tc + slotB] = wtB;
    }
}

// ---------------- MoE GEMM1: hid = silu(gather(hn) @ w1[e]) -----------------
__global__ __launch_bounds__(NTHR) void k_moe1(const float* __restrict__ W, int e) {
    int cnt = g_ecnt[e];
    int by = blockIdx.y;
    if (by * GBM >= cnt) return;
    __shared__ __align__(16) u16 Ah[GBM * A_LD], Al[GBM * A_LD];
    __shared__ __align__(16) u16 Bh[GBK * B_LD], Bl[GBK * B_LD];
    __shared__ float sc[8 * 256];                  // per-warp 16x16 f32 scratch
    __shared__ int toks[GBM];
    int tid = threadIdx.x, lane = tid & 31, wid = tid >> 5;
    int wm = wid >> 2, wn = wid & 3;
    if (tid < GBM) {
        int r = by * GBM + tid;
        toks[tid] = g_etok[e * Tc + (r < cnt ? r : cnt - 1)];
    }
    __syncthreads();
    const float* Bb = W + (size_t)blockIdx.x * GBN;
    AccFrag acc[4][2];
#pragma unroll
    for (int mb = 0; mb < 4; mb++)
#pragma unroll
        for (int nb = 0; nb < 2; nb++) wmma::fill_fragment(acc[mb][nb], 0.f);
    for (int k0 = 0; k0 < DIMc; k0 += GBK) {
#pragma unroll
        for (int i = 0; i < 4; i++) {                // gathered A tile + split
            int idx = tid + i * NTHR;
            int r = idx >> 3, c4 = (idx & 7) << 2;
            const float* arow = g_hn + (size_t)toks[r] * DIMc;
            float4 v = *(const float4*)(arow + k0 + c4);
            split_store(Ah + r * A_LD + c4, Al + r * A_LD + c4, v);
        }
        stage_b(Bh, Bl, Bb, HIDc, k0, tid);
        __syncthreads();
        wmma_chunk(Ah, Al, Bh, Bl, acc, wm, wn);
        __syncthreads();
    }
    float* wsc = sc + wid * 256;
#pragma unroll
    for (int mb = 0; mb < 4; mb++)
#pragma unroll
        for (int nb = 0; nb < 2; nb++) {
            wmma::store_matrix_sync(wsc, acc[mb][nb], 16, wmma::mem_row_major);
            __syncwarp();
            int rowbase = by * GBM + wm * 64 + mb * 16;
            int colbase = blockIdx.x * GBN + wn * 32 + nb * 16;
#pragma unroll
            for (int i = 0; i < 8; i++) {
                int idx = i * 32 + lane;
                int r = idx >> 4, c = idx & 15;
                int grow = rowbase + r;
                if (grow < cnt) {
                    float v = wsc[idx];
                    float s = v / (1.f + expf(-v));
                    u32 hb = f2b(s);
                    u32 lb = f2b(s - b2f(hb));
                    g_hid_h[(size_t)grow * HIDc + colbase + c] = (u16)hb;
                    g_hid_l[(size_t)grow * HIDc + colbase + c] = (u16)lb;
                }
            }
            __syncwarp();
        }
}

// ---------------- MoE GEMM2: mo[tok] += w * (hid @ w2[e]) -------------------
__global__ __launch_bounds__(NTHR) void k_moe2(const float* __restrict__ W, int e) {
    int cnt = g_ecnt[e];
    int by = blockIdx.y;
    if (by * GBM >= cnt) return;
    __shared__ __align__(16) u16 Ah[GBM * A_LD], Al[GBM * A_LD];
    __shared__ __align__(16) u16 Bh[GBK * B_LD], Bl[GBK * B_LD];
    __shared__ float sc[8 * 256];
    __shared__ int toks[GBM];
    __shared__ float wr[GBM];
    int tid = threadIdx.x, lane = tid & 31, wid = tid >> 5;
    int wm = wid >> 2, wn = wid & 3;
    if (tid < GBM) {
        int r = by * GBM + tid;
        int rc = (r < cnt ? r : cnt - 1);
        toks[tid] = g_etok[e * Tc + rc];
        wr[tid]   = g_ewgt[e * Tc + rc];
    }
    __syncthreads();
    const float* Bb = W + (size_t)blockIdx.x * GBN;
    AccFrag acc[4][2];
#pragma unroll
    for (int mb = 0; mb < 4; mb++)
#pragma unroll
        for (int nb = 0; nb < 2; nb++) wmma::fill_fragment(acc[mb][nb], 0.f);
    for (int k0 = 0; k0 < HIDc; k0 += GBK) {
#pragma unroll
        for (int i = 0; i < 4; i++) {                // A tile: bf16 hi/lo direct copy
            int idx = tid + i * NTHR;
            int r = idx >> 3, c4 = (idx & 7) << 2;
            int rg = by * GBM + r;
            if (rg >= cnt) rg = cnt - 1;
            *(uint2*)&Ah[r * A_LD + c4] =
                *(const uint2*)&g_hid_h[(size_t)rg * HIDc + k0 + c4];
            *(uint2*)&Al[r * A_LD + c4] =
                *(const uint2*)&g_hid_l[(size_t)rg * HIDc + k0 + c4];
        }
        stage_b(Bh, Bl, Bb, DIMc, k0, tid);
        __syncthreads();
        wmma_chunk(Ah, Al, Bh, Bl, acc, wm, wn);
        __syncthreads();
    }
    float* wsc = sc + wid * 256;
#pragma unroll
    for (int mb = 0; mb < 4; mb++)
#pragma unroll
        for (int nb = 0; nb < 2; nb++) {
            wmma::store_matrix_sync(wsc, acc[mb][nb], 16, wmma::mem_row_major);
            __syncwarp();
            int colbase = blockIdx.x * GBN + wn * 32 + nb * 16;
#pragma unroll
            for (int i = 0; i < 8; i++) {
                int idx = i * 32 + lane;
                int r = idx >> 4, c = idx & 15;
                int lr = wm * 64 + mb * 16 + r;
                int grow = by * GBM + lr;
                if (grow < cnt) {
                    g_mo[(size_t)toks[lr] * DIMc + colbase + c] += wr[lr] * wsc[idx];
                }
            }
            __syncwarp();
        }
}

// ---------------- launch ----------------------------------------------------
extern "C" void kernel_launch(void* const* d_in, const int* in_sizes, int n_in,
                              void* d_out, int out_size) {
    const float* x   = (const float*)d_in[0];
    const float* n1w = (const float*)d_in[1];
    const float* wq  = (const float*)d_in[2];
    const float* wk  = (const float*)d_in[3];
    const float* wv  = (const float*)d_in[4];
    const float* wo  = (const float*)d_in[5];
    const float* n2w = (const float*)d_in[6];
    const float* rw  = (const float*)d_in[7];
    const float* w1  = (const float*)d_in[8];
    const float* w2  = (const float*)d_in[9];
    float* out = (float*)d_out;

    float *p_xn, *p_q, *p_k, *p_v, *p_ao, *p_h, *p_hn;
    cudaGetSymbolAddress((void**)&p_xn, g_xn);
    cudaGetSymbolAddress((void**)&p_q,  g_q);
    cudaGetSymbolAddress((void**)&p_k,  g_k);
    cudaGetSymbolAddress((void**)&p_v,  g_v);
    cudaGetSymbolAddress((void**)&p_ao, g_ao);
    cudaGetSymbolAddress((void**)&p_h,  g_h);
    cudaGetSymbolAddress((void**)&p_hn, g_hn);

    // flash-attention dynamic smem (>48KB needs opt-in; idempotent)
    const int FA_SMEM = (16 * (FA_BQ + 4) + 16 * (FA_BK + 4) +
                         64 * (FA_BQ + 4) + 64 * (HDc + 4)) * (int)sizeof(float);
    cudaFuncSetAttribute(k_flash, cudaFuncAttributeMaxDynamicSharedMemorySize, FA_SMEM);

    dim3 blk(NTHR);
    const int EW = (Tc * DIMc + 255) / 256;

    k_ropetab<<<(Lc * 64 + 255) / 256, 256>>>();
    k_zero<<<EW, 256>>>();

    // rmsnorm1 + QKV projections (bf16x3 WMMA GEMM)
    k_rmsnorm<<<Tc, 256>>>(x, n1w, p_xn);
    k_gemm_bf3<<<dim3(DIMc / GBN, Tc / GBM), blk>>>(p_xn, wq, p_q, DIMc, DIMc, DIMc, DIMc);
    k_gemm_bf3<<<dim3(KVDc / GBN, Tc / GBM), blk>>>(p_xn, wk, p_k, DIMc, DIMc, KVDc, KVDc);
    k_gemm_bf3<<<dim3(KVDc / GBN, Tc / GBM), blk>>>(p_xn, wv, p_v, DIMc, DIMc, KVDc, KVDc);

    // RoPE
    k_rope<<<(Tc * Hc * 64 + 255) / 256, 256>>>(p_q, Hc);
    k_rope<<<(Tc * KVHc * 64 + 255) / 256, 256>>>(p_k, KVHc);

    // fused causal attention
    k_flash<<<dim3(1, Lc / FA_BQ, Bc * Hc), blk, FA_SMEM>>>();

    // o-proj + residual + rmsnorm2
    k_gemm_bf3<<<dim3(DIMc / GBN, Tc / GBM), blk>>>(p_ao, wo, p_q, DIMc, DIMc, DIMc, DIMc);
    k_add<<<EW, 256>>>(x);
    k_rmsnorm<<<Tc, 256>>>(p_h, n2w, p_hn);

    // MoE
    k_router<<<Tc, 256>>>(rw);
    for (int e = 0; e < Ec; e++) {
        k_moe1<<<dim3(HIDc / GBN, Tc / GBM), blk>>>(w1 + (size_t)e * DIMc * HIDc, e);
        k_moe2<<<dim3(DIMc / GBN, Tc / GBM), blk>>>(w2 + (size_t)e * HIDc * DIMc, e);
    }

    k_final<<<EW, 256>>>(out);
}